// round 4
// baseline (speedup 1.0000x reference)
#include <cuda_runtime.h>
#include <cstdint>

#define N_BATCH 64
#define T_SEQ   2000
#define DQ      256
#define NTOK    10
#define NJ      80
#define TILE    64
#define NTILES  32            // ceil(2000/64) -> 31*64+16
#define THREADS 256
#define SCALE_LG 0.17677669529663687f  // 1/sqrt(32)

#define OUT_ELEMS (N_BATCH * T_SEQ * DQ)

// smem layout (77,056 B -> 2 CTAs/SM):
//   [0     , 66560) sX   : 64 rows x 260 floats (1040B stride, LDS.128 conflict-free)
//                   sAttn: alias float[64*81] (post-compute)
//   [66560 , 76800) sVh  : vh as ull[10*128]
//   [76800 , 77056) sIdx : int[64]
#define XSTRIDE_F 260
#define XSTRIDE_U 130
#define OFF_V   66560
#define OFF_IDX 76800
#define SMEM_BYTES 77056

__device__ float g_Wqk[NJ * DQ];     // fused tanh(embed)@Wk^T ∘ Wq, pre-scaled
__device__ float g_vh[NTOK * DQ];    // tanh(embed)@Wv^T
__device__ int   g_idx_is64;

typedef unsigned long long ull;

__device__ __forceinline__ void fma2(ull& acc, ull a, ull b) {
    asm("fma.rn.f32x2 %0, %1, %2, %0;" : "+l"(acc) : "l"(a), "l"(b));
}
__device__ __forceinline__ float2 u2f2(ull v) {
    float2 r; asm("mov.b64 {%0, %1}, %2;" : "=f"(r.x), "=f"(r.y) : "l"(v)); return r;
}
__device__ __forceinline__ ull dupf(float a) {
    ull r; asm("mov.b64 %0, {%1, %1};" : "=l"(r) : "f"(a)); return r;
}

// =====================================================================
// Precompute: Wqk, vh, int64-vs-int32 detection (unchanged)
// =====================================================================
__global__ void precompute_kernel(const float* __restrict__ embed,
                                  const float* __restrict__ Wq,
                                  const float* __restrict__ Wk,
                                  const float* __restrict__ Wv,
                                  const int*   __restrict__ pidx) {
    __shared__ float skeys[NTOK * 32];
    const int tid = threadIdx.x;
    for (int e = tid; e < NTOK * 32; e += 256)
        skeys[e] = tanhf(embed[e]);
    __syncthreads();

    const int b = blockIdx.x;
    if (b < NJ) {
        const int h = b / NTOK, k = b % NTOK;
        __shared__ float skm[32];
        if (tid < 32) {
            const int u = h * 32 + tid;
            float s = 0.f;
            #pragma unroll
            for (int d = 0; d < 32; ++d) s += skeys[k * 32 + d] * Wk[u * 32 + d];
            skm[tid] = s;
        }
        __syncthreads();
        const int i = tid;
        float s = 0.f;
        #pragma unroll
        for (int d = 0; d < 32; ++d) s += skm[d] * Wq[(h * 32 + d) * DQ + i];
        g_Wqk[b * DQ + i] = s * SCALE_LG;
    } else {
        for (int e = tid; e < NTOK * DQ; e += 256) {
            const int k = e >> 8, u = e & 255;
            float s = 0.f;
            #pragma unroll
            for (int d = 0; d < 32; ++d) s += skeys[k * 32 + d] * Wv[u * 32 + d];
            g_vh[k * DQ + u] = s;
        }
        if (tid == 0) {
            int is64 = 1;
            for (int t = 1; t < 512; t += 2)
                if (pidx[t] != 0) { is64 = 0; break; }
            g_idx_is64 = is64;
        }
    }
}

// =====================================================================
// Main kernel: one 64-row tile per CTA, 8 warps = 8 heads, lane = row,
// 2 rows/lane (lane, lane+32). W streamed via __ldg uniform loads.
// =====================================================================
__global__ void __launch_bounds__(THREADS, 2)
attn_kernel(const float* __restrict__ inputs, const int* __restrict__ pidx,
            const float* __restrict__ ptab, float* __restrict__ out,
            float* __restrict__ scores)
{
    extern __shared__ char smem[];
    float* sXf   = (float*)(smem);
    ull*   sXu   = (ull*)(smem);
    float* sAttn = (float*)(smem);              // alias, used post-compute
    ull*   sVh   = (ull*)(smem + OFF_V);
    int*   sIdx  = (int*)(smem + OFF_IDX);

    const int tid  = threadIdx.x;
    const int lane = tid & 31;
    const int head = tid >> 5;        // warp id = head
    const int t0   = blockIdx.x * TILE;
    const int n    = blockIdx.y;
    const int nrows = min(TILE, T_SEQ - t0);
    const int is64  = g_idx_is64;

    // ---- prologue: vh -> smem, index gather ----
    {
        const float4* vsrc = (const float4*)g_vh;
        float4* vdst = (float4*)sVh;
        #pragma unroll
        for (int e = tid; e < NTOK * DQ / 4; e += THREADS) vdst[e] = vsrc[e];
        if (tid < TILE) {
            int v = 0;
            if (tid < nrows) {
                const int pos = n * T_SEQ + t0 + tid;
                v = is64 ? pidx[2 * pos] : pidx[pos];
            }
            sIdx[tid] = v;
        }
    }
    __syncthreads();

    // ---- stage full tile: x = inputs + pos_table[idx], 64 x 256 ----
    {
        const int sl = tid & 63;      // col slot: cols 4sl..4sl+3
        const int rg = tid >> 6;      // 0..3
        #pragma unroll 4
        for (int m = 0; m < 16; ++m) {
            const int r = rg + (m << 2);
            float4 v = make_float4(0.f, 0.f, 0.f, 0.f);
            if (r < nrows) {
                const float4 a = *(const float4*)(inputs + (size_t)(n * T_SEQ + t0 + r) * DQ + (sl << 2));
                const float4 b = *(const float4*)(ptab   + (size_t)sIdx[r] * DQ + (sl << 2));
                v.x = a.x + b.x; v.y = a.y + b.y; v.z = a.z + b.z; v.w = a.w + b.w;
            }
            *(float4*)(sXf + r * XSTRIDE_F + (sl << 2)) = v;
        }
    }
    __syncthreads();

    // ---- logits: acc[2 rows][10 toks], W via uniform __ldg ----
    ull acc[2][NTOK];
    #pragma unroll
    for (int jj = 0; jj < 2; ++jj)
        #pragma unroll
        for (int k = 0; k < NTOK; ++k) acc[jj][k] = 0ull;

    const ull* wbase = (const ull*)g_Wqk + (size_t)head * NTOK * 128;
    const ull* xb    = sXu + lane * XSTRIDE_U;

    #pragma unroll 2
    for (int ii = 0; ii < 64; ++ii) {
        const ulonglong2 xv0 = *(const ulonglong2*)(xb + 2 * ii);
        const ulonglong2 xv1 = *(const ulonglong2*)(xb + 32 * XSTRIDE_U + 2 * ii);
        #pragma unroll
        for (int k = 0; k < NTOK; ++k) {
            const ulonglong2 wv = __ldg((const ulonglong2*)(wbase + k * 128 + 2 * ii));
            fma2(acc[0][k], xv0.x, wv.x);
            fma2(acc[0][k], xv0.y, wv.y);
            fma2(acc[1][k], xv1.x, wv.x);
            fma2(acc[1][k], xv1.y, wv.y);
        }
    }
    __syncthreads();   // all reads of sX done before sAttn overwrites it

    // ---- softmax (10-wide, in-register) + scores + attn->smem ----
    #pragma unroll
    for (int jj = 0; jj < 2; ++jj) {
        float lg[NTOK];
        #pragma unroll
        for (int k = 0; k < NTOK; ++k) {
            const float2 f = u2f2(acc[jj][k]);
            lg[k] = f.x + f.y;
        }
        float mx = lg[0];
        #pragma unroll
        for (int k = 1; k < NTOK; ++k) mx = fmaxf(mx, lg[k]);
        float s = 0.f;
        float at[NTOK];
        #pragma unroll
        for (int k = 0; k < NTOK; ++k) { at[k] = __expf(lg[k] - mx); s += at[k]; }
        const float inv = 1.0f / s;
        #pragma unroll
        for (int k = 0; k < NTOK; ++k) at[k] *= inv;

        const int r = (jj << 5) + lane;          // 0..63
        #pragma unroll
        for (int k = 0; k < NTOK; ++k) sAttn[r * 81 + head * NTOK + k] = at[k];
        if (r < nrows) {
            float* sp = scores + ((size_t)n * NJ + head * NTOK) * T_SEQ + t0 + r;
            #pragma unroll
            for (int k = 0; k < NTOK; ++k) sp[k * T_SEQ] = at[k];
        }
    }
    __syncthreads();

    // ---- out = attn @ vh, float4 coalesced stores ----
    const int cg = tid & 63;          // cols 4*cg..4*cg+3
    const int eh = cg >> 3;           // owning head
    const int rr0 = tid >> 6;         // 0..3
    for (int r = rr0; r < nrows; r += 4) {
        const float* ar = sAttn + r * 81 + eh * NTOK;
        ull o0 = 0ull, o1 = 0ull;
        #pragma unroll
        for (int k = 0; k < NTOK; ++k) {
            const ull a2 = dupf(ar[k]);
            const ulonglong2 vv = *(const ulonglong2*)(sVh + k * 128 + cg * 2);
            fma2(o0, a2, vv.x);
            fma2(o1, a2, vv.y);
        }
        const float2 f0 = u2f2(o0), f1 = u2f2(o1);
        *(float4*)(out + (size_t)(n * T_SEQ + t0 + r) * DQ + (cg << 2)) =
            make_float4(f0.x, f0.y, f1.x, f1.y);
    }
}

extern "C" void kernel_launch(void* const* d_in, const int* in_sizes, int n_in,
                              void* d_out, int out_size) {
    const float* inputs = (const float*)d_in[0];
    const int*   pidx   = (const int*)d_in[1];
    const float* embed  = (const float*)d_in[2];
    const float* Wq     = (const float*)d_in[3];
    const float* Wk     = (const float*)d_in[4];
    const float* Wv     = (const float*)d_in[5];
    const float* ptab   = (const float*)d_in[6];

    float* out    = (float*)d_out;
    float* scores = (float*)d_out + OUT_ELEMS;

    cudaFuncSetAttribute(attn_kernel, cudaFuncAttributeMaxDynamicSharedMemorySize, SMEM_BYTES);

    precompute_kernel<<<NJ + 1, 256>>>(embed, Wq, Wk, Wv, pidx);
    attn_kernel<<<dim3(NTILES, N_BATCH), THREADS, SMEM_BYTES>>>(inputs, pidx, ptab, out, scores);
}

// round 6
// speedup vs baseline: 1.2057x; 1.2057x over previous
#include <cuda_runtime.h>
#include <cuda_bf16.h>
#include <cstdint>

typedef unsigned long long ull;
typedef unsigned int uint;

#define N_BATCH 64
#define T_SEQ   2000
#define DQ      256
#define NTOK    10
#define NJ      80
#define TILE    128
#define NTILES  16
#define THREADS 256
#define SCALE_LG 0.17677669529663687f
#define OUT_ELEMS (N_BATCH * T_SEQ * DQ)

// ---- smem map (230,400 B, 1 CTA/SM) ----
// A: 128 rows x 128 (hi,lo) uint2 pairs, row stride 1056B (132 uint2, 264 words ≡ 8 mod 32)
// B: 80 rows, same stride.  Logits/attn alias A after MMA (stride 85 floats).
#define STRA    132          // row stride in uint2 units (1056 B)
#define SLSTR   85           // logits/attn row stride in floats (odd -> conflict-free row reads)
#define OFF_B   135168       // 128*1056
#define OFF_VH  219648       // OFF_B + 80*1056
#define OFF_IDX 229888       // OFF_VH + 10240
#define SMEM_BYTES 230400

__device__ uint2 g_B[NJ * 128];     // Wqk bf16 {hi,lo} pairs, [80][128]
__device__ float g_vh[NTOK * DQ];
__device__ int   g_idx_is64;

// ---------- helpers ----------
__device__ __forceinline__ void fma2(ull& acc, ull a, ull b) {
    asm("fma.rn.f32x2 %0, %1, %2, %0;" : "+l"(acc) : "l"(a), "l"(b));
}
__device__ __forceinline__ float2 u2f2(ull v) {
    float2 r; asm("mov.b64 {%0, %1}, %2;" : "=f"(r.x), "=f"(r.y) : "l"(v)); return r;
}
__device__ __forceinline__ ull dupf(float a) {
    ull r; asm("mov.b64 %0, {%1, %1};" : "=l"(r) : "f"(a)); return r;
}
// pack two fp32 -> bf16x2 (lower half = x0)
__device__ __forceinline__ uint packbf(float x0, float x1) {
    uint r; asm("cvt.rn.bf16x2.f32 %0, %1, %2;" : "=r"(r) : "f"(x1), "f"(x0)); return r;
}
__device__ __forceinline__ float2 bf2f(uint u) {
    __nv_bfloat162 h = *reinterpret_cast<__nv_bfloat162*>(&u);
    return __bfloat1622float2(h);
}
__device__ __forceinline__ void mma16816(float* c,
    uint a0, uint a1, uint a2, uint a3, uint b0, uint b1) {
    asm volatile("mma.sync.aligned.m16n8k16.row.col.f32.bf16.bf16.f32 "
        "{%0,%1,%2,%3}, {%4,%5,%6,%7}, {%8,%9}, {%0,%1,%2,%3};"
        : "+f"(c[0]), "+f"(c[1]), "+f"(c[2]), "+f"(c[3])
        : "r"(a0), "r"(a1), "r"(a2), "r"(a3), "r"(b0), "r"(b1));
}

// =====================================================================
// Precompute: Wqk row b -> bf16 {hi,lo} pairs into g_B; vh; idx dtype.
// =====================================================================
__global__ void precompute_kernel(const float* __restrict__ embed,
                                  const float* __restrict__ Wq,
                                  const float* __restrict__ Wk,
                                  const float* __restrict__ Wv,
                                  const int*   __restrict__ pidx) {
    __shared__ float skeys[NTOK * 32];
    const int tid = threadIdx.x;
    for (int e = tid; e < NTOK * 32; e += 256) skeys[e] = tanhf(embed[e]);
    __syncthreads();

    const int b = blockIdx.x;
    if (b < NJ) {
        const int h = b / NTOK, k = b % NTOK;
        __shared__ float skm[32];
        if (tid < 32) {
            float s = 0.f;
            #pragma unroll
            for (int d = 0; d < 32; ++d) s += skeys[k * 32 + d] * Wk[(h * 32 + tid) * 32 + d];
            skm[tid] = s;
        }
        __syncthreads();
        if (tid < 128) {
            const int c0 = 2 * tid;
            float s0 = 0.f, s1 = 0.f;
            #pragma unroll
            for (int d = 0; d < 32; ++d) {
                const float km = skm[d];
                s0 += km * Wq[(h * 32 + d) * DQ + c0];
                s1 += km * Wq[(h * 32 + d) * DQ + c0 + 1];
            }
            s0 *= SCALE_LG; s1 *= SCALE_LG;
            const uint hi = packbf(s0, s1);
            const float2 f = bf2f(hi);
            const uint lo = packbf(s0 - f.x, s1 - f.y);
            g_B[b * 128 + tid] = make_uint2(hi, lo);
        }
    } else {
        for (int e = tid; e < NTOK * DQ; e += 256) {
            const int k = e >> 8, u = e & 255;
            float s = 0.f;
            #pragma unroll
            for (int d = 0; d < 32; ++d) s += skeys[k * 32 + d] * Wv[u * 32 + d];
            g_vh[k * DQ + u] = s;
        }
        if (tid == 0) {
            int is64 = 1;
            for (int t = 1; t < 512; t += 2)
                if (pidx[t] != 0) { is64 = 0; break; }
            g_idx_is64 = is64;
        }
    }
}

// =====================================================================
// Main kernel: 128-row tile; bf16 hi/lo split logits GEMM on mma.sync.
// =====================================================================
__global__ void __launch_bounds__(THREADS, 1)
attn_kernel(const float* __restrict__ inputs, const int* __restrict__ pidx,
            const float* __restrict__ ptab, float* __restrict__ out,
            float* __restrict__ scores)
{
    extern __shared__ char smem[];
    uint2* sA  = (uint2*)smem;
    uint2* sB  = (uint2*)(smem + OFF_B);
    float* sLog = (float*)smem;                 // alias A after MMA
    int*   sIdx = (int*)(smem + OFF_IDX);

    const int tid  = threadIdx.x;
    const int lane = tid & 31;
    const int w    = tid >> 5;
    const int gr   = lane >> 2;     // fragment group row 0..7
    const int q    = lane & 3;      // thread-in-group
    const int t0   = blockIdx.x * TILE;
    const int n    = blockIdx.y;
    const int nrows = min(TILE, T_SEQ - t0);
    const int is64  = g_idx_is64;

    // ---- prologue: B (re-strided), vh, idx ----
    {
        #pragma unroll 4
        for (int e = tid; e < NJ * 128; e += THREADS) {
            const int row = e >> 7, p = e & 127;
            sB[row * STRA + p] = g_B[e];
        }
        uint4* vd = (uint4*)(smem + OFF_VH);
        const uint4* vs = (const uint4*)g_vh;
        for (int e = tid; e < NTOK * DQ / 4; e += THREADS) vd[e] = vs[e];
        if (tid < TILE) {
            int v = 0;
            if (tid < nrows) {
                const int pos = n * T_SEQ + t0 + tid;
                v = is64 ? pidx[2 * pos] : pidx[pos];
            }
            sIdx[tid] = v;
        }
    }
    __syncthreads();

    // ---- stage A: x = inputs + ptab[idx] -> bf16 {hi,lo} interleaved ----
    {
        const int sl = tid & 63;    // float4 col slot (cols 4sl..4sl+3)
        const int rg = tid >> 6;    // 0..3
        #pragma unroll 4
        for (int m = 0; m < 32; ++m) {
            const int r = rg + 4 * m;
            float4 a = make_float4(0.f, 0.f, 0.f, 0.f), b = a;
            if (r < nrows) {
                a = *(const float4*)(inputs + (size_t)(n * T_SEQ + t0 + r) * DQ + (sl << 2));
                b = *(const float4*)(ptab   + (size_t)sIdx[r] * DQ + (sl << 2));
            }
            const float x0 = a.x + b.x, x1 = a.y + b.y, x2 = a.z + b.z, x3 = a.w + b.w;
            const uint h01 = packbf(x0, x1), h23 = packbf(x2, x3);
            const float2 f01 = bf2f(h01), f23 = bf2f(h23);
            const uint l01 = packbf(x0 - f01.x, x1 - f01.y);
            const uint l23 = packbf(x2 - f23.x, x3 - f23.y);
            *(uint4*)(smem + (size_t)r * 1056 + sl * 16) = make_uint4(h01, l01, h23, l23);
        }
    }
    __syncthreads();

    // ---- MMA: warp w -> rows [16w,16w+16), 10 n-tiles, 16 k-steps ----
    float acc[10][4];
    #pragma unroll
    for (int j = 0; j < 10; ++j)
        #pragma unroll
        for (int i = 0; i < 4; ++i) acc[j][i] = 0.f;

    {
        const uint2* a0p = sA + (w * 16 + gr) * STRA + q;
        const uint2* a1p = a0p + 8 * STRA;
        const uint2* bp  = sB + gr * STRA + q;
        #pragma unroll 2
        for (int ks = 0; ks < 16; ++ks) {
            const uint2 A0 = a0p[ks * 8];
            const uint2 A2 = a0p[ks * 8 + 4];
            const uint2 A1 = a1p[ks * 8];
            const uint2 A3 = a1p[ks * 8 + 4];
            #pragma unroll
            for (int j = 0; j < 10; ++j) {
                const uint2 B0 = bp[j * 8 * STRA + ks * 8];
                const uint2 B1 = bp[j * 8 * STRA + ks * 8 + 4];
                mma16816(acc[j], A0.x, A1.x, A2.x, A3.x, B0.x, B1.x);
                mma16816(acc[j], A0.x, A1.x, A2.x, A3.x, B0.y, B1.y);
                mma16816(acc[j], A0.y, A1.y, A2.y, A3.y, B0.x, B1.x);
            }
        }
    }
    __syncthreads();   // all A/B reads done before logits overwrite A

    // ---- fragments -> sLog (stride 85 floats, conflict-free) ----
    {
        const int r0 = w * 16 + gr;
        #pragma unroll
        for (int j = 0; j < 10; ++j) {
            const int c = 8 * j + 2 * q;
            sLog[r0 * SLSTR + c]           = acc[j][0];
            sLog[r0 * SLSTR + c + 1]       = acc[j][1];
            sLog[(r0 + 8) * SLSTR + c]     = acc[j][2];
            sLog[(r0 + 8) * SLSTR + c + 1] = acc[j][3];
        }
    }
    __syncthreads();

    // ---- softmax: warps 0-3, lane = row; attn written back in place ----
    if (w < 4) {
        const int r = w * 32 + lane;
        float* row = sLog + r * SLSTR;
        float* sp = scores + ((size_t)n * NJ) * T_SEQ + t0 + r;
        #pragma unroll
        for (int h = 0; h < 8; ++h) {
            float lg[NTOK];
            #pragma unroll
            for (int k = 0; k < NTOK; ++k) lg[k] = row[h * NTOK + k];
            float mx = lg[0];
            #pragma unroll
            for (int k = 1; k < NTOK; ++k) mx = fmaxf(mx, lg[k]);
            float s = 0.f, at[NTOK];
            #pragma unroll
            for (int k = 0; k < NTOK; ++k) { at[k] = __expf(lg[k] - mx); s += at[k]; }
            const float inv = 1.0f / s;
            #pragma unroll
            for (int k = 0; k < NTOK; ++k) {
                at[k] *= inv;
                row[h * NTOK + k] = at[k];
            }
            if (r < nrows) {
                #pragma unroll
                for (int k = 0; k < NTOK; ++k) sp[(size_t)(h * NTOK + k) * T_SEQ] = at[k];
            }
        }
    }
    __syncthreads();

    // ---- out = attn @ vh: vh cached in regs (8 cols/thread) ----
    {
        const int cb = tid & 31;       // cols [8cb, 8cb+8)
        const int rg = tid >> 5;       // 0..7
        const int h = cb >> 2;
        const ull* vptr = (const ull*)(smem + OFF_VH);
        ull vv[NTOK][4];
        #pragma unroll
        for (int k = 0; k < NTOK; ++k)
            #pragma unroll
            for (int i = 0; i < 4; ++i) vv[k][i] = vptr[k * 128 + cb * 4 + i];

        #pragma unroll 2
        for (int m = 0; m < 16; ++m) {
            const int r = rg + m * 8;
            const float* ar = sLog + r * SLSTR + h * NTOK;
            ull o0 = 0, o1 = 0, o2 = 0, o3 = 0;
            #pragma unroll
            for (int k = 0; k < NTOK; ++k) {
                const ull a2 = dupf(ar[k]);
                fma2(o0, a2, vv[k][0]); fma2(o1, a2, vv[k][1]);
                fma2(o2, a2, vv[k][2]); fma2(o3, a2, vv[k][3]);
            }
            if (r < nrows) {
                const float2 f0 = u2f2(o0), f1 = u2f2(o1), f2 = u2f2(o2), f3 = u2f2(o3);
                float* op = out + (size_t)(n * T_SEQ + t0 + r) * DQ + cb * 8;
                *(float4*)(op)     = make_float4(f0.x, f0.y, f1.x, f1.y);
                *(float4*)(op + 4) = make_float4(f2.x, f2.y, f3.x, f3.y);
            }
        }
    }
}

extern "C" void kernel_launch(void* const* d_in, const int* in_sizes, int n_in,
                              void* d_out, int out_size) {
    const float* inputs = (const float*)d_in[0];
    const int*   pidx   = (const int*)d_in[1];
    const float* embed  = (const float*)d_in[2];
    const float* Wq     = (const float*)d_in[3];
    const float* Wk     = (const float*)d_in[4];
    const float* Wv     = (const float*)d_in[5];
    const float* ptab   = (const float*)d_in[6];

    float* out    = (float*)d_out;
    float* scores = (float*)d_out + OUT_ELEMS;

    cudaFuncSetAttribute(attn_kernel, cudaFuncAttributeMaxDynamicSharedMemorySize, SMEM_BYTES);

    precompute_kernel<<<NJ + 1, 256>>>(embed, Wq, Wk, Wv, pidx);
    attn_kernel<<<dim3(NTILES, N_BATCH), THREADS, SMEM_BYTES>>>(inputs, pidx, ptab, out, scores);
}

// round 7
// speedup vs baseline: 1.8300x; 1.5178x over previous
#include <cuda_runtime.h>
#include <cuda_bf16.h>
#include <cstdint>

typedef unsigned long long ull;
typedef unsigned int uint;

#define N_BATCH 64
#define T_SEQ   2000
#define DQ      256
#define NTOK    10
#define NJ      80
#define TILE    64
#define NC      8            // chunks per CTA: 4 tiles x 2 k-halves
#define THREADS 512
#define SCALE_LG 0.17677669529663687f
#define OUT_ELEMS (N_BATCH * T_SEQ * DQ)

// ---- smem map (187,136 B, 1 CTA/SM, 16 warps) ----
#define XSTR   68            // uint2 per X row (544 B; 136 words = 8 mod 32 -> conflict-free)
#define XBYTES 34816         // 64 * 544
#define OFF_X0 0
#define OFF_X1 34816
#define OFF_LOG 69632        // 64 x 85 floats = 21760
#define SLSTR  85
#define OFF_B  91392         // 80 x 1056 = 84480
#define BSTR   132           // uint2 per B row
#define OFF_VH 175872        // 10240
#define OFF_IDX 186112       // 256 ints
#define SMEM_BYTES 187136

__device__ uint2 g_B[NJ * 128];     // Wqk bf16 {hi,lo} pairs, [80][128]
__device__ float g_vh[NTOK * DQ];
__device__ int   g_idx_is64;

// ---------- helpers ----------
__device__ __forceinline__ void fma2(ull& acc, ull a, ull b) {
    asm("fma.rn.f32x2 %0, %1, %2, %0;" : "+l"(acc) : "l"(a), "l"(b));
}
__device__ __forceinline__ float2 u2f2(ull v) {
    float2 r; asm("mov.b64 {%0, %1}, %2;" : "=f"(r.x), "=f"(r.y) : "l"(v)); return r;
}
__device__ __forceinline__ ull dupf(float a) {
    ull r; asm("mov.b64 %0, {%1, %1};" : "=l"(r) : "f"(a)); return r;
}
__device__ __forceinline__ uint packbf(float x0, float x1) {
    uint r; asm("cvt.rn.bf16x2.f32 %0, %1, %2;" : "=r"(r) : "f"(x1), "f"(x0)); return r;
}
__device__ __forceinline__ float2 bf2f(uint u) {
    __nv_bfloat162 h = *reinterpret_cast<__nv_bfloat162*>(&u);
    return __bfloat1622float2(h);
}
__device__ __forceinline__ void mma16816(float* c,
    uint a0, uint a1, uint a2, uint a3, uint b0, uint b1) {
    asm volatile("mma.sync.aligned.m16n8k16.row.col.f32.bf16.bf16.f32 "
        "{%0,%1,%2,%3}, {%4,%5,%6,%7}, {%8,%9}, {%0,%1,%2,%3};"
        : "+f"(c[0]), "+f"(c[1]), "+f"(c[2]), "+f"(c[3])
        : "r"(a0), "r"(a1), "r"(a2), "r"(a3), "r"(b0), "r"(b1));
}

// =====================================================================
// Precompute: Wqk row b -> bf16 {hi,lo} pairs into g_B; vh; idx dtype.
// =====================================================================
__global__ void precompute_kernel(const float* __restrict__ embed,
                                  const float* __restrict__ Wq,
                                  const float* __restrict__ Wk,
                                  const float* __restrict__ Wv,
                                  const int*   __restrict__ pidx) {
    __shared__ float skeys[NTOK * 32];
    const int tid = threadIdx.x;
    for (int e = tid; e < NTOK * 32; e += 256) skeys[e] = tanhf(embed[e]);
    __syncthreads();

    const int b = blockIdx.x;
    if (b < NJ) {
        const int h = b / NTOK, k = b % NTOK;
        __shared__ float skm[32];
        if (tid < 32) {
            float s = 0.f;
            #pragma unroll
            for (int d = 0; d < 32; ++d) s += skeys[k * 32 + d] * Wk[(h * 32 + tid) * 32 + d];
            skm[tid] = s;
        }
        __syncthreads();
        if (tid < 128) {
            const int c0 = 2 * tid;
            float s0 = 0.f, s1 = 0.f;
            #pragma unroll
            for (int d = 0; d < 32; ++d) {
                const float km = skm[d];
                s0 += km * Wq[(h * 32 + d) * DQ + c0];
                s1 += km * Wq[(h * 32 + d) * DQ + c0 + 1];
            }
            s0 *= SCALE_LG; s1 *= SCALE_LG;
            const uint hi = packbf(s0, s1);
            const float2 f = bf2f(hi);
            const uint lo = packbf(s0 - f.x, s1 - f.y);
            g_B[b * 128 + tid] = make_uint2(hi, lo);
        }
    } else {
        for (int e = tid; e < NTOK * DQ; e += 256) {
            const int k = e >> 8, u = e & 255;
            float s = 0.f;
            #pragma unroll
            for (int d = 0; d < 32; ++d) s += skeys[k * 32 + d] * Wv[u * 32 + d];
            g_vh[k * DQ + u] = s;
        }
        if (tid == 0) {
            int is64 = 1;
            for (int t = 1; t < 512; t += 2)
                if (pidx[t] != 0) { is64 = 0; break; }
            g_idx_is64 = is64;
        }
    }
}

// ---- pipeline stage helpers ----
__device__ __forceinline__ void ldg_chunk(
    const float* __restrict__ inputs, const float* __restrict__ ptab,
    const int* __restrict__ sIdx, int n, int base, int cc, int sl, int rq,
    float4* ra, float4* rb)
{
    const int sc = cc >> 1;
    const int col0 = (cc & 1) * 128 + sl * 4;
    const int nr = min(TILE, T_SEQ - base - sc * 64);
    #pragma unroll
    for (int m = 0; m < 4; ++m) {
        const int r = rq + m * 16;
        ra[m] = make_float4(0.f, 0.f, 0.f, 0.f);
        rb[m] = ra[m];
        if (r < nr) {
            ra[m] = *(const float4*)(inputs + (size_t)(n * T_SEQ + base + sc * 64 + r) * DQ + col0);
            rb[m] = *(const float4*)(ptab + (size_t)sIdx[sc * 64 + r] * DQ + col0);
        }
    }
}

__device__ __forceinline__ void sts_chunk(char* smem, int pbuf, int sl, int rq,
                                          const float4* ra, const float4* rb)
{
    #pragma unroll
    for (int m = 0; m < 4; ++m) {
        const int r = rq + m * 16;
        const float x0 = ra[m].x + rb[m].x, x1 = ra[m].y + rb[m].y;
        const float x2 = ra[m].z + rb[m].z, x3 = ra[m].w + rb[m].w;
        const uint h01 = packbf(x0, x1), h23 = packbf(x2, x3);
        const float2 f01 = bf2f(h01), f23 = bf2f(h23);
        const uint l01 = packbf(x0 - f01.x, x1 - f01.y);
        const uint l23 = packbf(x2 - f23.x, x3 - f23.y);
        *(uint4*)(smem + pbuf * XBYTES + r * 544 + sl * 16) = make_uint4(h01, l01, h23, l23);
    }
}

// =====================================================================
// Main kernel: 4 tiles of 64 rows per CTA; 2 k-chunks per tile, double-
// buffered; LDG of chunk c+1 overlaps MMA of chunk c.
// =====================================================================
__global__ void __launch_bounds__(THREADS, 1)
attn_kernel(const float* __restrict__ inputs, const int* __restrict__ pidx,
            const float* __restrict__ ptab, float* __restrict__ out,
            float* __restrict__ scores)
{
    extern __shared__ char smem[];
    uint2* sB   = (uint2*)(smem + OFF_B);
    float* sLog = (float*)(smem + OFF_LOG);
    int*   sIdx = (int*)(smem + OFF_IDX);

    const int tid  = threadIdx.x;
    const int lane = tid & 31;
    const int w    = tid >> 5;
    const int n    = blockIdx.y;
    const int base = blockIdx.x * 256;   // 4 tiles x 64 rows

    // mma mapping: 4 row-groups x 4 n-splits (3/3/2/2 of 10 n-tiles)
    const int rg4  = w & 3;
    const int ns   = w >> 2;
    const int jt0  = (ns < 2) ? 3 * ns : (6 + 2 * (ns - 2));
    const int jcnt = (ns < 2) ? 3 : 2;
    const int gr   = lane >> 2, q = lane & 3;
    const int sl   = tid & 31, rq = tid >> 5;

    // ---- prologue: B, vh, all 4 tiles' idx ----
    {
        #pragma unroll 4
        for (int e = tid; e < NJ * 128; e += THREADS)
            sB[(e >> 7) * BSTR + (e & 127)] = g_B[e];
        uint4* vd = (uint4*)(smem + OFF_VH);
        const uint4* vs = (const uint4*)g_vh;
        for (int e = tid; e < NTOK * DQ / 4; e += THREADS) vd[e] = vs[e];
        const int is64 = g_idx_is64;
        if (tid < 256) {
            const int t = base + tid;
            int v = 0;
            if (t < T_SEQ) {
                const int pos = n * T_SEQ + t;
                v = is64 ? pidx[2 * pos] : pidx[pos];
            }
            sIdx[tid] = v;
        }
    }
    __syncthreads();

    // stage chunk 0
    {
        float4 ra[4], rb[4];
        ldg_chunk(inputs, ptab, sIdx, n, base, 0, sl, rq, ra, rb);
        sts_chunk(smem, 0, sl, rq, ra, rb);
    }
    __syncthreads();

    float acc[3][4];
    #pragma unroll
    for (int j = 0; j < 3; ++j)
        #pragma unroll
        for (int i = 0; i < 4; ++i) acc[j][i] = 0.f;

    #pragma unroll 2
    for (int c = 0; c < NC; ++c) {
        const int p = c & 1;
        const int sc = c >> 1;

        // A) issue LDGs for chunk c+1 (in flight under MMA)
        float4 ra[4], rb[4];
        if (c < NC - 1) ldg_chunk(inputs, ptab, sIdx, n, base, c + 1, sl, rq, ra, rb);

        // B) MMA chunk c
        {
            const uint2* xb = (const uint2*)(smem + p * XBYTES);
            const uint2* a0p = xb + (rg4 * 16 + gr) * XSTR + q;
            const uint2* a1p = a0p + 8 * XSTR;
            #pragma unroll
            for (int ks = 0; ks < 8; ++ks) {
                const uint2 A0 = a0p[ks * 8];
                const uint2 A2 = a0p[ks * 8 + 4];
                const uint2 A1 = a1p[ks * 8];
                const uint2 A3 = a1p[ks * 8 + 4];
                const int gk = (c & 1) * 8 + ks;
                #pragma unroll
                for (int j = 0; j < 3; ++j) {
                    if (j < jcnt) {
                        const uint2* bp = sB + ((jt0 + j) * 8 + gr) * BSTR + gk * 8 + q;
                        const uint2 B0 = bp[0];
                        const uint2 B1 = bp[4];
                        mma16816(acc[j], A0.x, A1.x, A2.x, A3.x, B0.x, B1.x);
                        mma16816(acc[j], A0.x, A1.x, A2.x, A3.x, B0.y, B1.y);
                        mma16816(acc[j], A0.y, A1.y, A2.y, A3.y, B0.x, B1.x);
                    }
                }
            }
        }

        // C) tile complete: fragments -> sLog, reset acc
        if (c & 1) {
            const int r0 = rg4 * 16 + gr;
            #pragma unroll
            for (int j = 0; j < 3; ++j) {
                if (j < jcnt) {
                    const int cc2 = (jt0 + j) * 8 + 2 * q;
                    sLog[r0 * SLSTR + cc2]           = acc[j][0];
                    sLog[r0 * SLSTR + cc2 + 1]       = acc[j][1];
                    sLog[(r0 + 8) * SLSTR + cc2]     = acc[j][2];
                    sLog[(r0 + 8) * SLSTR + cc2 + 1] = acc[j][3];
                }
                #pragma unroll
                for (int i = 0; i < 4; ++i) acc[j][i] = 0.f;
            }
        }
        __syncthreads();   // D

        // E) store staged chunk c+1
        if (c < NC - 1) sts_chunk(smem, p ^ 1, sl, rq, ra, rb);

        // F) softmax + scores + out epilogue for tile sc
        if (c & 1) {
            __syncthreads();
            {
                const int r = tid & 63;
                const int h = tid >> 6;
                const int nr = min(TILE, T_SEQ - base - sc * 64);
                float* row = sLog + r * SLSTR + h * NTOK;
                float lg[NTOK];
                #pragma unroll
                for (int k = 0; k < NTOK; ++k) lg[k] = row[k];
                float mx = lg[0];
                #pragma unroll
                for (int k = 1; k < NTOK; ++k) mx = fmaxf(mx, lg[k]);
                float s = 0.f, at[NTOK];
                #pragma unroll
                for (int k = 0; k < NTOK; ++k) { at[k] = __expf(lg[k] - mx); s += at[k]; }
                const float inv = 1.0f / s;
                #pragma unroll
                for (int k = 0; k < NTOK; ++k) { at[k] *= inv; row[k] = at[k]; }
                if (r < nr) {
                    float* sp = scores + ((size_t)n * NJ + h * NTOK) * T_SEQ + base + sc * 64 + r;
                    #pragma unroll
                    for (int k = 0; k < NTOK; ++k) sp[(size_t)k * T_SEQ] = at[k];
                }
            }
            __syncthreads();
            {
                const int cb = tid & 63;     // cols [4cb, 4cb+4)
                const int rgq = tid >> 6;    // 0..7
                const int h = cb >> 3;
                const int nr = min(TILE, T_SEQ - base - sc * 64);
                const ull* vptr = (const ull*)(smem + OFF_VH);
                ull vv[NTOK][2];
                #pragma unroll
                for (int k = 0; k < NTOK; ++k) {
                    vv[k][0] = vptr[k * 128 + cb * 2];
                    vv[k][1] = vptr[k * 128 + cb * 2 + 1];
                }
                #pragma unroll
                for (int m = 0; m < 8; ++m) {
                    const int r = rgq + m * 8;
                    const float* ar = sLog + r * SLSTR + h * NTOK;
                    ull o0 = 0, o1 = 0;
                    #pragma unroll
                    for (int k = 0; k < NTOK; ++k) {
                        const ull a2 = dupf(ar[k]);
                        fma2(o0, a2, vv[k][0]);
                        fma2(o1, a2, vv[k][1]);
                    }
                    if (r < nr) {
                        const float2 f0 = u2f2(o0), f1 = u2f2(o1);
                        *(float4*)(out + (size_t)(n * T_SEQ + base + sc * 64 + r) * DQ + cb * 4) =
                            make_float4(f0.x, f0.y, f1.x, f1.y);
                    }
                }
            }
        }
        __syncthreads();   // G
    }
}

extern "C" void kernel_launch(void* const* d_in, const int* in_sizes, int n_in,
                              void* d_out, int out_size) {
    const float* inputs = (const float*)d_in[0];
    const int*   pidx   = (const int*)d_in[1];
    const float* embed  = (const float*)d_in[2];
    const float* Wq     = (const float*)d_in[3];
    const float* Wk     = (const float*)d_in[4];
    const float* Wv     = (const float*)d_in[5];
    const float* ptab   = (const float*)d_in[6];

    float* out    = (float*)d_out;
    float* scores = (float*)d_out + OUT_ELEMS;

    cudaFuncSetAttribute(attn_kernel, cudaFuncAttributeMaxDynamicSharedMemorySize, SMEM_BYTES);

    precompute_kernel<<<NJ + 1, 256>>>(embed, Wq, Wk, Wv, pidx);
    attn_kernel<<<dim3(8, N_BATCH), THREADS, SMEM_BYTES>>>(inputs, pidx, ptab, out, scores);
}

// round 8
// speedup vs baseline: 2.2280x; 1.2175x over previous
#include <cuda_runtime.h>
#include <cuda_bf16.h>
#include <cstdint>

typedef unsigned long long ull;
typedef unsigned int uint;

#define N_BATCH 64
#define T_SEQ   2000
#define DQ      256
#define NTOK    10
#define NJ      80
#define NJT     10           // n8 tiles
#define TILE    64
#define NC      8            // 4 tiles x 2 k-chunks
#define THREADS 256
#define SCALE_LG 0.17677669529663687f
#define OUT_ELEMS (N_BATCH * T_SEQ * DQ)

// ---- smem (80,896 B/CTA -> 2 CTAs/SM) ----
#define XSTR   68            // uint2 per X row (544 B)
#define XBYTES 34816
#define OFF_X1 34816
#define OFF_VH 69632
#define OFF_IDX 79872
#define SMEM_BYTES 80896
#define SLSTR  85            // sLog aliases X buffer 1

__device__ uint4 g_Bf[NJT * 16 * 32];   // Wqk bf16 hi/lo in MMA fragment order
__device__ float g_vh[NTOK * DQ];
__device__ int   g_idx_is64;

// ---------- helpers ----------
__device__ __forceinline__ void fma2(ull& acc, ull a, ull b) {
    asm("fma.rn.f32x2 %0, %1, %2, %0;" : "+l"(acc) : "l"(a), "l"(b));
}
__device__ __forceinline__ float2 u2f2(ull v) {
    float2 r; asm("mov.b64 {%0, %1}, %2;" : "=f"(r.x), "=f"(r.y) : "l"(v)); return r;
}
__device__ __forceinline__ ull dupf(float a) {
    ull r; asm("mov.b64 %0, {%1, %1};" : "=l"(r) : "f"(a)); return r;
}
__device__ __forceinline__ uint packbf(float x0, float x1) {
    uint r; asm("cvt.rn.bf16x2.f32 %0, %1, %2;" : "=r"(r) : "f"(x1), "f"(x0)); return r;
}
__device__ __forceinline__ float2 bf2f(uint u) {
    __nv_bfloat162 h = *reinterpret_cast<__nv_bfloat162*>(&u);
    return __bfloat1622float2(h);
}
__device__ __forceinline__ void mma16816(float* c,
    uint a0, uint a1, uint a2, uint a3, uint b0, uint b1) {
    asm volatile("mma.sync.aligned.m16n8k16.row.col.f32.bf16.bf16.f32 "
        "{%0,%1,%2,%3}, {%4,%5,%6,%7}, {%8,%9}, {%0,%1,%2,%3};"
        : "+f"(c[0]), "+f"(c[1]), "+f"(c[2]), "+f"(c[3])
        : "r"(a0), "r"(a1), "r"(a2), "r"(a3), "r"(b0), "r"(b1));
}

// =====================================================================
// Precompute: Wqk row b -> bf16 {hi,lo} scattered into fragment order.
// =====================================================================
__global__ void precompute_kernel(const float* __restrict__ embed,
                                  const float* __restrict__ Wq,
                                  const float* __restrict__ Wk,
                                  const float* __restrict__ Wv,
                                  const int*   __restrict__ pidx) {
    __shared__ float skeys[NTOK * 32];
    const int tid = threadIdx.x;
    for (int e = tid; e < NTOK * 32; e += 256) skeys[e] = tanhf(embed[e]);
    __syncthreads();

    const int b = blockIdx.x;
    if (b < NJ) {
        const int h = b / NTOK, k = b % NTOK;
        __shared__ float skm[32];
        if (tid < 32) {
            float s = 0.f;
            #pragma unroll
            for (int d = 0; d < 32; ++d) s += skeys[k * 32 + d] * Wk[(h * 32 + tid) * 32 + d];
            skm[tid] = s;
        }
        __syncthreads();
        if (tid < 128) {          // col-pair tid -> cols 2tid, 2tid+1
            const int c0 = 2 * tid;
            float s0 = 0.f, s1 = 0.f;
            #pragma unroll
            for (int d = 0; d < 32; ++d) {
                const float km = skm[d];
                s0 += km * Wq[(h * 32 + d) * DQ + c0];
                s1 += km * Wq[(h * 32 + d) * DQ + c0 + 1];
            }
            s0 *= SCALE_LG; s1 *= SCALE_LG;
            const uint hi = packbf(s0, s1);
            const float2 f = bf2f(hi);
            const uint lo = packbf(s0 - f.x, s1 - f.y);
            // fragment-order scatter: lane = gr*4+q, uint4 = {B0hi,B0lo,B1hi,B1lo}
            const int j = b >> 3, gr = b & 7;
            const int gk = tid >> 3, qq = tid & 7;
            const int q = qq & 3, hf = qq >> 2;
            uint* dst = (uint*)&g_Bf[(j * 16 + gk) * 32 + gr * 4 + q];
            dst[hf * 2]     = hi;
            dst[hf * 2 + 1] = lo;
        }
    } else {
        for (int e = tid; e < NTOK * DQ; e += 256) {
            const int k = e >> 8, u = e & 255;
            float s = 0.f;
            #pragma unroll
            for (int d = 0; d < 32; ++d) s += skeys[k * 32 + d] * Wv[u * 32 + d];
            g_vh[k * DQ + u] = s;
        }
        if (tid == 0) {
            int is64 = 1;
            for (int t = 1; t < 512; t += 2)
                if (pidx[t] != 0) { is64 = 0; break; }
            g_idx_is64 = is64;
        }
    }
}

// ---- staging helpers (256 threads, 64x128 chunk) ----
__device__ __forceinline__ void ldg_chunk(
    const float* __restrict__ inputs, const float* __restrict__ ptab,
    const int* __restrict__ sIdx, int n, int base, int cc, int sl, int rq,
    float4* ra, float4* rb)
{
    const int sc = cc >> 1;
    const int col0 = (cc & 1) * 128 + sl * 4;
    const int nr = min(TILE, T_SEQ - base - sc * 64);
    #pragma unroll
    for (int m = 0; m < 8; ++m) {
        const int r = rq + m * 8;
        ra[m] = make_float4(0.f, 0.f, 0.f, 0.f);
        rb[m] = ra[m];
        if (r < nr) {
            ra[m] = *(const float4*)(inputs + (size_t)(n * T_SEQ + base + sc * 64 + r) * DQ + col0);
            rb[m] = *(const float4*)(ptab + (size_t)sIdx[sc * 64 + r] * DQ + col0);
        }
    }
}

__device__ __forceinline__ void sts_chunk(char* smem, int pbuf, int sl, int rq,
                                          const float4* ra, const float4* rb)
{
    #pragma unroll
    for (int m = 0; m < 8; ++m) {
        const int r = rq + m * 8;
        const float x0 = ra[m].x + rb[m].x, x1 = ra[m].y + rb[m].y;
        const float x2 = ra[m].z + rb[m].z, x3 = ra[m].w + rb[m].w;
        const uint h01 = packbf(x0, x1), h23 = packbf(x2, x3);
        const float2 f01 = bf2f(h01), f23 = bf2f(h23);
        const uint l01 = packbf(x0 - f01.x, x1 - f01.y);
        const uint l23 = packbf(x2 - f23.x, x3 - f23.y);
        *(uint4*)(smem + pbuf * XBYTES + r * 544 + sl * 16) = make_uint4(h01, l01, h23, l23);
    }
}

// =====================================================================
// Main kernel: 4 tiles x 64 rows per CTA, 2 CTAs/SM, B via L2 __ldg.
// =====================================================================
__global__ void __launch_bounds__(THREADS, 2)
attn_kernel(const float* __restrict__ inputs, const int* __restrict__ pidx,
            const float* __restrict__ ptab, float* __restrict__ out,
            float* __restrict__ scores)
{
    extern __shared__ char smem[];
    float* sLog = (float*)(smem + OFF_X1);     // aliases X buffer 1
    int*   sIdx = (int*)(smem + OFF_IDX);

    const int tid  = threadIdx.x;
    const int lane = tid & 31;
    const int w    = tid >> 5;          // 0..7
    const int rg4  = w & 3;
    const int jt0  = (w >> 2) * 5;      // n-split: n-tiles [jt0, jt0+5)
    const int gr   = lane >> 2, q = lane & 3;
    const int sl   = tid & 31, rq = tid >> 5;
    const int n    = blockIdx.y;
    const int base = blockIdx.x * 256;

    // ---- prologue: vh, idx ----
    {
        uint4* vd = (uint4*)(smem + OFF_VH);
        const uint4* vs = (const uint4*)g_vh;
        for (int e = tid; e < NTOK * DQ / 4; e += THREADS) vd[e] = vs[e];
        const int is64 = g_idx_is64;
        const int t = base + tid;
        int v = 0;
        if (t < T_SEQ) {
            const int pos = n * T_SEQ + t;
            v = is64 ? pidx[2 * pos] : pidx[pos];
        }
        sIdx[tid] = v;
    }
    __syncthreads();

    // stage chunk 0
    {
        float4 ra[8], rb[8];
        ldg_chunk(inputs, ptab, sIdx, n, base, 0, sl, rq, ra, rb);
        sts_chunk(smem, 0, sl, rq, ra, rb);
    }
    __syncthreads();

    float acc[5][4];
    #pragma unroll
    for (int j = 0; j < 5; ++j)
        #pragma unroll
        for (int i = 0; i < 4; ++i) acc[j][i] = 0.f;

    #pragma unroll 2
    for (int c = 0; c < NC; ++c) {
        const int p = c & 1;
        const int sc = c >> 1;

        // A) LDGs for chunk c+1, in flight under MMA
        float4 ra[8], rb[8];
        if (c < NC - 1) ldg_chunk(inputs, ptab, sIdx, n, base, c + 1, sl, rq, ra, rb);

        // B) MMA chunk c: A from smem, B fragments from L2
        {
            const uint2* a0p = (const uint2*)(smem + p * XBYTES) + (rg4 * 16 + gr) * XSTR + q;
            const uint2* a1p = a0p + 8 * XSTR;
            #pragma unroll
            for (int ks = 0; ks < 8; ++ks) {
                const uint2 A0 = a0p[ks * 8];
                const uint2 A2 = a0p[ks * 8 + 4];
                const uint2 A1 = a1p[ks * 8];
                const uint2 A3 = a1p[ks * 8 + 4];
                const int gk = p * 8 + ks;
                #pragma unroll
                for (int j = 0; j < 5; ++j) {
                    const uint4 bf = __ldg(&g_Bf[((jt0 + j) * 16 + gk) * 32 + lane]);
                    mma16816(acc[j], A0.x, A1.x, A2.x, A3.x, bf.x, bf.z);
                    mma16816(acc[j], A0.x, A1.x, A2.x, A3.x, bf.y, bf.w);
                    mma16816(acc[j], A0.y, A1.y, A2.y, A3.y, bf.x, bf.z);
                }
            }
        }
        __syncthreads();   // D: MMA reads of buf p complete; prior epilogue done

        // C) tile done: fragments -> sLog (aliases buf1, just consumed)
        if (c & 1) {
            const int r0 = rg4 * 16 + gr;
            #pragma unroll
            for (int j = 0; j < 5; ++j) {
                const int cc2 = (jt0 + j) * 8 + 2 * q;
                sLog[r0 * SLSTR + cc2]           = acc[j][0];
                sLog[r0 * SLSTR + cc2 + 1]       = acc[j][1];
                sLog[(r0 + 8) * SLSTR + cc2]     = acc[j][2];
                sLog[(r0 + 8) * SLSTR + cc2 + 1] = acc[j][3];
                #pragma unroll
                for (int i = 0; i < 4; ++i) acc[j][i] = 0.f;
            }
        }

        // E) store staged chunk c+1 into buffer p^1
        if (c < NC - 1) sts_chunk(smem, p ^ 1, sl, rq, ra, rb);

        if (c & 1) {
            __syncthreads();   // frags + sts visible
            // F1) softmax + scores: r = tid&63, heads h0 and h0+4
            {
                const int r = tid & 63;
                const int h0 = tid >> 6;        // 0..3
                const int nr = min(TILE, T_SEQ - base - sc * 64);
                #pragma unroll
                for (int hh = 0; hh < 2; ++hh) {
                    const int h = h0 + hh * 4;
                    float* row = sLog + r * SLSTR + h * NTOK;
                    float lg[NTOK];
                    #pragma unroll
                    for (int k = 0; k < NTOK; ++k) lg[k] = row[k];
                    float mx = lg[0];
                    #pragma unroll
                    for (int k = 1; k < NTOK; ++k) mx = fmaxf(mx, lg[k]);
                    float s = 0.f, at[NTOK];
                    #pragma unroll
                    for (int k = 0; k < NTOK; ++k) { at[k] = __expf(lg[k] - mx); s += at[k]; }
                    const float inv = 1.0f / s;
                    #pragma unroll
                    for (int k = 0; k < NTOK; ++k) { at[k] *= inv; row[k] = at[k]; }
                    if (r < nr) {
                        float* sp = scores + ((size_t)n * NJ + h * NTOK) * T_SEQ + base + sc * 64 + r;
                        #pragma unroll
                        for (int k = 0; k < NTOK; ++k) sp[(size_t)k * T_SEQ] = at[k];
                    }
                }
            }
            __syncthreads();   // attn visible
            // F2) out = attn @ vh
            {
                const int cb = tid & 63;        // cols [4cb, 4cb+4)
                const int rgq = tid >> 6;       // 0..3
                const int h = cb >> 3;
                const int nr = min(TILE, T_SEQ - base - sc * 64);
                const ull* vptr = (const ull*)(smem + OFF_VH);
                ull vv[NTOK][2];
                #pragma unroll
                for (int k = 0; k < NTOK; ++k) {
                    vv[k][0] = vptr[k * 128 + cb * 2];
                    vv[k][1] = vptr[k * 128 + cb * 2 + 1];
                }
                #pragma unroll 4
                for (int m = 0; m < 16; ++m) {
                    const int r = rgq + m * 4;
                    const float* ar = sLog + r * SLSTR + h * NTOK;
                    ull o0 = 0, o1 = 0;
                    #pragma unroll
                    for (int k = 0; k < NTOK; ++k) {
                        const ull a2 = dupf(ar[k]);
                        fma2(o0, a2, vv[k][0]);
                        fma2(o1, a2, vv[k][1]);
                    }
                    if (r < nr) {
                        const float2 f0 = u2f2(o0), f1 = u2f2(o1);
                        *(float4*)(out + (size_t)(n * T_SEQ + base + sc * 64 + r) * DQ + cb * 4) =
                            make_float4(f0.x, f0.y, f1.x, f1.y);
                    }
                }
            }
            // no trailing sync: next iteration's D covers the sLog hazard
        } else {
            __syncthreads();   // G: sts into buf1 visible before next MMA reads it
        }
    }
}

extern "C" void kernel_launch(void* const* d_in, const int* in_sizes, int n_in,
                              void* d_out, int out_size) {
    const float* inputs = (const float*)d_in[0];
    const int*   pidx   = (const int*)d_in[1];
    const float* embed  = (const float*)d_in[2];
    const float* Wq     = (const float*)d_in[3];
    const float* Wk     = (const float*)d_in[4];
    const float* Wv     = (const float*)d_in[5];
    const float* ptab   = (const float*)d_in[6];

    float* out    = (float*)d_out;
    float* scores = (float*)d_out + OUT_ELEMS;

    cudaFuncSetAttribute(attn_kernel, cudaFuncAttributeMaxDynamicSharedMemorySize, SMEM_BYTES);

    precompute_kernel<<<NJ + 1, 256>>>(embed, Wq, Wk, Wv, pidx);
    attn_kernel<<<dim3(8, N_BATCH), THREADS, SMEM_BYTES>>>(inputs, pidx, ptab, out, scores);
}